// round 4
// baseline (speedup 1.0000x reference)
#include <cuda_runtime.h>
#include <stdint.h>

// Problem shape (fixed by the dataset): B=1, N=100000, E=3200000, H=8, D=64
#define NN 100000
#define HH 8
#define DD 64
#define EE 3200000
#define TOT (EE*HH)     // 25,600,000 output elements

// Scratch (static device arrays; no allocation allowed)
__device__ float    g_a_self[NN*HH];
__device__ float    g_a_adjc[NN*HH];
__device__ unsigned g_M[NN*HH];   // order-encoded max of a_adjc per (target node, head)

// ---------------------------------------------------------------------------
// Threefry-2x32 (20 rounds), key = (0, 42), counter = (0, j).
// JAX partitionable layout (threefry_partitionable=True):
//   bits(j) = x0 ^ x1   (XOR-fold of the two output words, prng.py bit_width<64 path)
//   keep(j) = bit31(bits) == 0   (uniform < 0.5, exact)
// Key schedule with k0 = 0, k1 = 42:
//   ks  = [0, 42, 0x1BD11BDA ^ 42]
// ---------------------------------------------------------------------------
__device__ __forceinline__ unsigned tf_xor(unsigned j) {
  const unsigned K1  = 42u;
  const unsigned KS2 = 0x1BD11BDAu ^ 42u;
  unsigned x0 = 0u;        // c0 (=0) + ks[0] (=0)
  unsigned x1 = j + K1;    // c1 + ks[1]
#define TF_R(r) { x0 += x1; x1 = __funnelshift_l(x1, x1, (r)); x1 ^= x0; }
  TF_R(13) TF_R(15) TF_R(26) TF_R(6)
  x0 += K1;   x1 += KS2 + 1u;
  TF_R(17) TF_R(29) TF_R(16) TF_R(24)
  x0 += KS2;  x1 += 2u;              // + ks[0](=0) + 2
  TF_R(13) TF_R(15) TF_R(26) TF_R(6)
  /* x0 += ks[0] = 0 */ x1 += K1 + 3u;
  TF_R(17) TF_R(29) TF_R(16) TF_R(24)
  x0 += K1;   x1 += KS2 + 4u;
  TF_R(13) TF_R(15) TF_R(26) TF_R(6)
  x0 += KS2;  x1 += 5u;              // + ks[0](=0) + 5
#undef TF_R
  return x0 ^ x1;
}

// Order-preserving float->uint encoding for atomicMax
__device__ __forceinline__ unsigned enc_f(float f) {
  unsigned u = __float_as_uint(f);
  return (u & 0x80000000u) ? ~u : (u | 0x80000000u);
}
__device__ __forceinline__ float dec_f(unsigned k) {
  unsigned u = (k & 0x80000000u) ? (k ^ 0x80000000u) : ~k;
  return __uint_as_float(u);
}

// ---------------------------------------------------------------------------
__global__ void k_init_max() {
  int i = blockIdx.x * blockDim.x + threadIdx.x;
  if (i < NN*HH) g_M[i] = 0u;   // 0u encodes below every real float
}

// a_self/a_adjc = einsum('nhd,dh->nh'); one warp per (node,head), float2/lane
__global__ void k_dots(const float* __restrict__ X,
                       const float* __restrict__ Ws,
                       const float* __restrict__ Wa) {
  int n = blockIdx.x;
  int w = threadIdx.x >> 5;
  int l = threadIdx.x & 31;
  const float2 x = *reinterpret_cast<const float2*>(
      X + ((size_t)n * HH + w) * DD + 2*l);
  float ws0 = Ws[(2*l    ) * HH + w];
  float ws1 = Ws[(2*l + 1) * HH + w];
  float wa0 = Wa[(2*l    ) * HH + w];
  float wa1 = Wa[(2*l + 1) * HH + w];
  float ds = x.x * ws0 + x.y * ws1;
  float da = x.x * wa0 + x.y * wa1;
#pragma unroll
  for (int o = 16; o; o >>= 1) {
    ds += __shfl_down_sync(0xFFFFFFFFu, ds, o);
    da += __shfl_down_sync(0xFFFFFFFFu, da, o);
  }
  if (l == 0) {
    g_a_self[n*HH + w] = ds;
    g_a_adjc[n*HH + w] = da;
  }
}

// Segment max via atomicMax on order-encoded floats.
// leaky_relu is monotone and a_self[t] is segment-constant, so
// segment_max(leaky(a_self[t]+a_adjc[s])) == leaky(a_self[t] + max_s a_adjc[s]).
__global__ void k_edge_max(const int* __restrict__ targets,
                           const int* __restrict__ sources) {
  int i = blockIdx.x * blockDim.x + threadIdx.x;
  if (i >= TOT) return;
  int e = i >> 3;
  int h = i & 7;
  int t = targets[e];
  int s = sources[e];
  float v = g_a_adjc[s*8 + h];
  atomicMax(&g_M[t*8 + h], enc_f(v));
}

// out[j] = keep(j) ? 2*exp(e - m) : 0
//   e = leaky(a_self[t]+a_adjc[s]),  m = leaky(a_self[t]+max),  m2+eps == 1.0f
__device__ __forceinline__ float edge_val(float a_s, float a_a, unsigned menc,
                                          unsigned ybits) {
  float x  = a_s + a_a;
  float e  = (x  >= 0.0f) ? x  : 0.2f * x;
  float mx = a_s + dec_f(menc);
  float m  = (mx >= 0.0f) ? mx : 0.2f * mx;
  float v  = __expf(e - m) * 2.0f;
  return (ybits & 0x80000000u) ? 0.0f : v;
}

// Each thread: 2 adjacent outputs (same edge, even head) -> two independent
// threefry chains for ILP, float2 loads from the L2-resident tables, float2 store.
__global__ void k_out(const int* __restrict__ targets,
                      const int* __restrict__ sources,
                      float* __restrict__ out) {
  unsigned tI = blockIdx.x * blockDim.x + threadIdx.x;  // 0 .. TOT/2-1
  if (tI >= (unsigned)(TOT/2)) return;
  unsigned j0 = 2u * tI;

  unsigned b0 = tf_xor(j0);
  unsigned b1 = tf_xor(j0 + 1u);

  int e = (int)(j0 >> 3);
  int h = (int)(j0 & 7u);        // even
  int t = targets[e];
  int s = sources[e];
  float2 as = *reinterpret_cast<const float2*>(g_a_self + t*8 + h);
  float2 aa = *reinterpret_cast<const float2*>(g_a_adjc + s*8 + h);
  uint2  me = *reinterpret_cast<const uint2 *>(g_M      + t*8 + h);

  float2 o;
  o.x = edge_val(as.x, aa.x, me.x, b0);
  o.y = edge_val(as.y, aa.y, me.y, b1);
  *reinterpret_cast<float2*>(out + j0) = o;
}

// ---------------------------------------------------------------------------
extern "C" void kernel_launch(void* const* d_in, const int* in_sizes, int n_in,
                              void* d_out, int out_size) {
  const float* X  = (const float*)d_in[0];
  const float* Ws = (const float*)d_in[1];
  const float* Wa = (const float*)d_in[2];
  // input order: X, Wself, Wadjc, [N scalar], targets, sources, degree
  int ti = (n_in >= 6 && in_sizes[3] == 1) ? 4 : 3;
  const int* targets = (const int*)d_in[ti];
  const int* sources = (const int*)d_in[ti + 1];
  float* out = (float*)d_out;

  k_init_max<<<(NN*HH + 255) / 256, 256>>>();
  k_dots    <<<NN, 256>>>(X, Ws, Wa);
  k_edge_max<<<TOT / 256, 256>>>(targets, sources);
  k_out     <<<(TOT/2) / 256, 256>>>(targets, sources, out);
}

// round 5
// speedup vs baseline: 1.0756x; 1.0756x over previous
#include <cuda_runtime.h>
#include <stdint.h>

// Problem shape (fixed by the dataset): B=1, N=100000, E=3200000, H=8, D=64
#define NN 100000
#define HH 8
#define DD 64
#define EE 3200000
#define TOT (EE*HH)     // 25,600,000 output elements

// Scratch (static device arrays; no allocation allowed). 16B-aligned for vec I/O.
__device__ __align__(16) float    g_a_self[NN*HH];
__device__ __align__(16) float    g_a_adjc[NN*HH];
__device__ __align__(16) unsigned g_M[NN*HH];   // order-encoded per-(target,head) max

// ---------------------------------------------------------------------------
// Threefry-2x32 (20 rounds), key=(0,42), ctr=(0,j), JAX partitionable:
//   bits(j) = x0 ^ x1 ;  keep(j) = bit31 == 0.
// All adds forced onto the IMAD (fma) pipe via mad.lo.u32 with an opaque 'one'
// so the alu pipe carries only the mandatory SHF+LOP3 (40 ops/eval).
// ---------------------------------------------------------------------------
__device__ __forceinline__ unsigned addm(unsigned a, unsigned one, unsigned b) {
  unsigned d;
  asm("mad.lo.u32 %0, %1, %2, %3;" : "=r"(d) : "r"(a), "r"(one), "r"(b));
  return d;
}
__device__ __forceinline__ unsigned tf_xor(unsigned j, unsigned one) {
  const unsigned K1  = 42u;
  const unsigned KS2 = 0x1BD11BDAu ^ 42u;
  unsigned x0 = 0u;                 // c0(=0) + ks0(=0)
  unsigned x1 = addm(j, one, K1);   // c1 + ks1
#define TF_R(r) { x0 = addm(x1, one, x0); x1 = __funnelshift_l(x1, x1, (r)); x1 ^= x0; }
  TF_R(13) TF_R(15) TF_R(26) TF_R(6)
  x0 = addm(one, K1, x0);   x1 = addm(one, KS2 + 1u, x1);
  TF_R(17) TF_R(29) TF_R(16) TF_R(24)
  x0 = addm(one, KS2, x0);  x1 = addm(one, 2u, x1);
  TF_R(13) TF_R(15) TF_R(26) TF_R(6)
  /* ks0 = 0 */             x1 = addm(one, K1 + 3u, x1);
  TF_R(17) TF_R(29) TF_R(16) TF_R(24)
  x0 = addm(one, K1, x0);   x1 = addm(one, KS2 + 4u, x1);
  TF_R(13) TF_R(15) TF_R(26) TF_R(6)
  x0 = addm(one, KS2, x0);  x1 = addm(one, 5u, x1);
#undef TF_R
  return x0 ^ x1;
}

// Order-preserving float->uint encoding for atomicMax
__device__ __forceinline__ unsigned enc_f(float f) {
  unsigned u = __float_as_uint(f);
  return (u & 0x80000000u) ? ~u : (u | 0x80000000u);
}
__device__ __forceinline__ float dec_f(unsigned k) {
  unsigned u = (k & 0x80000000u) ? (k ^ 0x80000000u) : ~k;
  return __uint_as_float(u);
}

// ---------------------------------------------------------------------------
__global__ void k_init_max() {
  int i = blockIdx.x * blockDim.x + threadIdx.x;
  if (i < NN*HH) g_M[i] = 0u;   // 0u encodes below every real float
}

// a_self/a_adjc = einsum('nhd,dh->nh'); one warp per (node,head), float2/lane
__global__ void k_dots(const float* __restrict__ X,
                       const float* __restrict__ Ws,
                       const float* __restrict__ Wa) {
  int n = blockIdx.x;
  int w = threadIdx.x >> 5;
  int l = threadIdx.x & 31;
  const float2 x = *reinterpret_cast<const float2*>(
      X + ((size_t)n * HH + w) * DD + 2*l);
  float ws0 = Ws[(2*l    ) * HH + w];
  float ws1 = Ws[(2*l + 1) * HH + w];
  float wa0 = Wa[(2*l    ) * HH + w];
  float wa1 = Wa[(2*l + 1) * HH + w];
  float ds = x.x * ws0 + x.y * ws1;
  float da = x.x * wa0 + x.y * wa1;
#pragma unroll
  for (int o = 16; o; o >>= 1) {
    ds += __shfl_down_sync(0xFFFFFFFFu, ds, o);
    da += __shfl_down_sync(0xFFFFFFFFu, da, o);
  }
  if (l == 0) {
    g_a_self[n*HH + w] = ds;
    g_a_adjc[n*HH + w] = da;
  }
}

// ---------------------------------------------------------------------------
// Segment max: one thread per EDGE, all 8 heads. Read current max first and
// only atomicMax when this edge can still win -> atomic count drops from
// 25.6M to ~O(N*H*ln(deg)). Stale reads are safe (redundant atomic at worst).
// ---------------------------------------------------------------------------
__global__ void k_edge_max(const int* __restrict__ targets,
                           const int* __restrict__ sources) {
  int e = blockIdx.x * blockDim.x + threadIdx.x;
  if (e >= EE) return;
  int t = targets[e];
  int s = sources[e];
  const float4 a0 = *reinterpret_cast<const float4*>(g_a_adjc + s*8);
  const float4 a1 = *reinterpret_cast<const float4*>(g_a_adjc + s*8 + 4);
  const uint4  m0 = *reinterpret_cast<const uint4 *>(g_M + t*8);
  const uint4  m1 = *reinterpret_cast<const uint4 *>(g_M + t*8 + 4);
  unsigned v;
  v = enc_f(a0.x); if (v > m0.x) atomicMax(&g_M[t*8 + 0], v);
  v = enc_f(a0.y); if (v > m0.y) atomicMax(&g_M[t*8 + 1], v);
  v = enc_f(a0.z); if (v > m0.z) atomicMax(&g_M[t*8 + 2], v);
  v = enc_f(a0.w); if (v > m0.w) atomicMax(&g_M[t*8 + 3], v);
  v = enc_f(a1.x); if (v > m1.x) atomicMax(&g_M[t*8 + 4], v);
  v = enc_f(a1.y); if (v > m1.y) atomicMax(&g_M[t*8 + 5], v);
  v = enc_f(a1.z); if (v > m1.z) atomicMax(&g_M[t*8 + 6], v);
  v = enc_f(a1.w); if (v > m1.w) atomicMax(&g_M[t*8 + 7], v);
}

// ---------------------------------------------------------------------------
// out[j] = keep(j) ? 2*exp(e - m) : 0
//   e = leaky(a_self[t]+a_adjc[s]),  m = leaky(a_self[t]+max),  m2+eps == 1.0f
// ---------------------------------------------------------------------------
__device__ __forceinline__ float edge_val(float a_s, float a_a, unsigned menc,
                                          unsigned ybits) {
  float x  = a_s + a_a;
  float e  = (x  >= 0.0f) ? x  : 0.2f * x;
  float mx = a_s + dec_f(menc);
  float m  = (mx >= 0.0f) ? mx : 0.2f * mx;
  float v  = __expf(e - m) * 2.0f;
  return (ybits & 0x80000000u) ? 0.0f : v;
}

__global__ void k_out(const int* __restrict__ targets,
                      const int* __restrict__ sources,
                      float* __restrict__ out, unsigned one) {
  unsigned tI = blockIdx.x * blockDim.x + threadIdx.x;  // 0 .. TOT/2-1
  if (tI >= (unsigned)(TOT/2)) return;
  unsigned j0 = 2u * tI;

  unsigned b0 = tf_xor(j0, one);
  unsigned b1 = tf_xor(j0 + 1u, one);

  int e = (int)(j0 >> 3);
  int h = (int)(j0 & 7u);        // even
  int t = targets[e];
  int s = sources[e];
  float2 as = *reinterpret_cast<const float2*>(g_a_self + t*8 + h);
  float2 aa = *reinterpret_cast<const float2*>(g_a_adjc + s*8 + h);
  uint2  me = *reinterpret_cast<const uint2 *>(g_M      + t*8 + h);

  float2 o;
  o.x = edge_val(as.x, aa.x, me.x, b0);
  o.y = edge_val(as.y, aa.y, me.y, b1);
  *reinterpret_cast<float2*>(out + j0) = o;
}

// ---------------------------------------------------------------------------
extern "C" void kernel_launch(void* const* d_in, const int* in_sizes, int n_in,
                              void* d_out, int out_size) {
  const float* X  = (const float*)d_in[0];
  const float* Ws = (const float*)d_in[1];
  const float* Wa = (const float*)d_in[2];
  // input order: X, Wself, Wadjc, [N scalar], targets, sources, degree
  int ti = (n_in >= 6 && in_sizes[3] == 1) ? 4 : 3;
  const int* targets = (const int*)d_in[ti];
  const int* sources = (const int*)d_in[ti + 1];
  float* out = (float*)d_out;

  k_init_max<<<(NN*HH + 255) / 256, 256>>>();
  k_dots    <<<NN, 256>>>(X, Ws, Wa);
  k_edge_max<<<(EE + 255) / 256, 256>>>(targets, sources);
  k_out     <<<(TOT/2) / 256, 256>>>(targets, sources, out, 1u);
}

// round 6
// speedup vs baseline: 1.9240x; 1.7888x over previous
#include <cuda_runtime.h>
#include <stdint.h>

// Problem shape (fixed by the dataset): B=1, N=100000, E=3200000, H=8, D=64
#define NN 100000
#define HH 8
#define DD 64
#define EE 3200000
#define TOT (EE*HH)     // 25,600,000 output elements

// Scratch (static device arrays). 16B-aligned for vec I/O.
__device__ __align__(16) float    g_a_self[NN*HH];
__device__ __align__(16) float    g_a_adjc[NN*HH];
__device__ __align__(16) unsigned g_M[NN*HH];   // order-encoded per-(target,head) max

// ---------------------------------------------------------------------------
// Threefry-2x32 (20 rounds), key=(0,42), ctr=(0,j), JAX partitionable:
//   bits(j) = x0 ^ x1 ;  keep(j) = bit31 == 0.
// Adds forced onto the IMAD (fma) pipe via mad.lo.u32 with an opaque 'one' so
// the alu pipe carries only the mandatory SHF+LOP3 (40 warp-ops/eval).
// ---------------------------------------------------------------------------
__device__ __forceinline__ unsigned addm(unsigned a, unsigned one, unsigned b) {
  unsigned d;
  asm("mad.lo.u32 %0, %1, %2, %3;" : "=r"(d) : "r"(a), "r"(one), "r"(b));
  return d;
}
__device__ __forceinline__ unsigned tf_xor(unsigned j, unsigned one) {
  const unsigned K1  = 42u;
  const unsigned KS2 = 0x1BD11BDAu ^ 42u;
  unsigned x0 = 0u;                 // c0(=0) + ks0(=0)
  unsigned x1 = addm(j, one, K1);   // c1 + ks1
#define TF_R(r) { x0 = addm(x1, one, x0); x1 = __funnelshift_l(x1, x1, (r)); x1 ^= x0; }
  TF_R(13) TF_R(15) TF_R(26) TF_R(6)
  x0 = addm(one, K1, x0);   x1 = addm(one, KS2 + 1u, x1);
  TF_R(17) TF_R(29) TF_R(16) TF_R(24)
  x0 = addm(one, KS2, x0);  x1 = addm(one, 2u, x1);
  TF_R(13) TF_R(15) TF_R(26) TF_R(6)
  /* ks0 = 0 */             x1 = addm(one, K1 + 3u, x1);
  TF_R(17) TF_R(29) TF_R(16) TF_R(24)
  x0 = addm(one, K1, x0);   x1 = addm(one, KS2 + 4u, x1);
  TF_R(13) TF_R(15) TF_R(26) TF_R(6)
  x0 = addm(one, KS2, x0);  x1 = addm(one, 5u, x1);
#undef TF_R
  return x0 ^ x1;
}

// Order-preserving float<->uint encoding for atomicMax
__device__ __forceinline__ unsigned enc_f(float f) {
  unsigned u = __float_as_uint(f);
  return (u & 0x80000000u) ? ~u : (u | 0x80000000u);
}
__device__ __forceinline__ float dec_f(unsigned k) {
  unsigned u = (k & 0x80000000u) ? (k ^ 0x80000000u) : ~k;
  return __uint_as_float(u);
}

// ---------------------------------------------------------------------------
// K1: a_self/a_adjc = einsum('nhd,dh->nh') + g_M zero-init, grid-stride with
// 4-node unroll per warp iteration (MLP=4, no CTA churn).
// One warp per head; lane l covers feature 2l,2l+1 (float2, coalesced 256B).
// ---------------------------------------------------------------------------
#define DOTS_GRID 592
#define DOTS_UN   4
__global__ void k_dots(const float* __restrict__ X,
                       const float* __restrict__ Ws,
                       const float* __restrict__ Wa) {
  int w = threadIdx.x >> 5;   // head
  int l = threadIdx.x & 31;
  // weights for this (head, lane) — L1-resident after first iteration
  float ws0 = Ws[(2*l    ) * HH + w];
  float ws1 = Ws[(2*l + 1) * HH + w];
  float wa0 = Wa[(2*l    ) * HH + w];
  float wa1 = Wa[(2*l + 1) * HH + w];

  for (int n0 = blockIdx.x * DOTS_UN; n0 < NN; n0 += DOTS_GRID * DOTS_UN) {
    float2 x[DOTS_UN];
    int nv = (n0 + DOTS_UN <= NN) ? DOTS_UN : (NN - n0);
#pragma unroll
    for (int u = 0; u < DOTS_UN; u++) {
      if (u < nv)
        x[u] = *reinterpret_cast<const float2*>(
            X + ((size_t)(n0 + u) * HH + w) * DD + 2*l);
    }
    float ds[DOTS_UN], da[DOTS_UN];
#pragma unroll
    for (int u = 0; u < DOTS_UN; u++) {
      if (u < nv) {
        ds[u] = x[u].x * ws0 + x[u].y * ws1;
        da[u] = x[u].x * wa0 + x[u].y * wa1;
      }
    }
#pragma unroll
    for (int o = 16; o; o >>= 1) {
#pragma unroll
      for (int u = 0; u < DOTS_UN; u++) {
        if (u < nv) {
          ds[u] += __shfl_down_sync(0xFFFFFFFFu, ds[u], o);
          da[u] += __shfl_down_sync(0xFFFFFFFFu, da[u], o);
        }
      }
    }
    if (l == 0) {
#pragma unroll
      for (int u = 0; u < DOTS_UN; u++) {
        if (u < nv) {
          g_a_self[(n0 + u)*HH + w] = ds[u];
          g_a_adjc[(n0 + u)*HH + w] = da[u];
        }
      }
    }
    // fold g_M init: warp 0 zeroes this iteration's nodes (8 heads via 8 lanes)
    if (w == 0 && l < 8 * DOTS_UN) {
      int u = l >> 3;
      if (u < nv) g_M[(n0 + u)*8 + (l & 7)] = 0u;
    }
  }
}

// ---------------------------------------------------------------------------
// K2: segment max. One thread per EDGE, all 8 heads; read current max first
// and only atomicMax when this edge can still win (stale read = safe).
// ---------------------------------------------------------------------------
__global__ void k_edge_max(const int* __restrict__ targets,
                           const int* __restrict__ sources) {
  int e = blockIdx.x * blockDim.x + threadIdx.x;
  if (e >= EE) return;
  int t = targets[e];
  int s = sources[e];
  const float4 a0 = *reinterpret_cast<const float4*>(g_a_adjc + s*8);
  const float4 a1 = *reinterpret_cast<const float4*>(g_a_adjc + s*8 + 4);
  const uint4  m0 = *reinterpret_cast<const uint4 *>(g_M + t*8);
  const uint4  m1 = *reinterpret_cast<const uint4 *>(g_M + t*8 + 4);
  unsigned v;
  v = enc_f(a0.x); if (v > m0.x) atomicMax(&g_M[t*8 + 0], v);
  v = enc_f(a0.y); if (v > m0.y) atomicMax(&g_M[t*8 + 1], v);
  v = enc_f(a0.z); if (v > m0.z) atomicMax(&g_M[t*8 + 2], v);
  v = enc_f(a0.w); if (v > m0.w) atomicMax(&g_M[t*8 + 3], v);
  v = enc_f(a1.x); if (v > m1.x) atomicMax(&g_M[t*8 + 4], v);
  v = enc_f(a1.y); if (v > m1.y) atomicMax(&g_M[t*8 + 5], v);
  v = enc_f(a1.z); if (v > m1.z) atomicMax(&g_M[t*8 + 6], v);
  v = enc_f(a1.w); if (v > m1.w) atomicMax(&g_M[t*8 + 7], v);
}

// ---------------------------------------------------------------------------
// K3: out[j] = keep(j) ? 2*exp(e - m) : 0
//   e = leaky(a_self[t]+a_adjc[s]),  m = leaky(a_self[t]+max),  m2+eps == 1.0f
// 4 outputs per thread (one edge, heads h..h+3): 4 independent threefry
// chains for ILP, float4 table loads (L2-resident), float4 store.
// ---------------------------------------------------------------------------
__device__ __forceinline__ float edge_val(float a_s, float a_a, unsigned menc,
                                          unsigned ybits) {
  float x  = a_s + a_a;
  float e  = (x  >= 0.0f) ? x  : 0.2f * x;
  float mx = a_s + dec_f(menc);
  float m  = (mx >= 0.0f) ? mx : 0.2f * mx;
  float v  = __expf(e - m) * 2.0f;
  return (ybits & 0x80000000u) ? 0.0f : v;
}

__global__ void k_out(const int* __restrict__ targets,
                      const int* __restrict__ sources,
                      float* __restrict__ out, unsigned one) {
  unsigned tI = blockIdx.x * blockDim.x + threadIdx.x;  // 0 .. TOT/4-1
  if (tI >= (unsigned)(TOT/4)) return;
  unsigned j0 = 4u * tI;

  unsigned b0 = tf_xor(j0,      one);
  unsigned b1 = tf_xor(j0 + 1u, one);
  unsigned b2 = tf_xor(j0 + 2u, one);
  unsigned b3 = tf_xor(j0 + 3u, one);

  int e = (int)(j0 >> 3);
  int h = (int)(j0 & 7u);        // 0 or 4
  int t = targets[e];
  int s = sources[e];
  float4 as = *reinterpret_cast<const float4*>(g_a_self + t*8 + h);
  float4 aa = *reinterpret_cast<const float4*>(g_a_adjc + s*8 + h);
  uint4  me = *reinterpret_cast<const uint4 *>(g_M      + t*8 + h);

  float4 o;
  o.x = edge_val(as.x, aa.x, me.x, b0);
  o.y = edge_val(as.y, aa.y, me.y, b1);
  o.z = edge_val(as.z, aa.z, me.z, b2);
  o.w = edge_val(as.w, aa.w, me.w, b3);
  *reinterpret_cast<float4*>(out + j0) = o;
}

// ---------------------------------------------------------------------------
extern "C" void kernel_launch(void* const* d_in, const int* in_sizes, int n_in,
                              void* d_out, int out_size) {
  const float* X  = (const float*)d_in[0];
  const float* Ws = (const float*)d_in[1];
  const float* Wa = (const float*)d_in[2];
  // input order: X, Wself, Wadjc, [N scalar], targets, sources, degree
  int ti = (n_in >= 6 && in_sizes[3] == 1) ? 4 : 3;
  const int* targets = (const int*)d_in[ti];
  const int* sources = (const int*)d_in[ti + 1];
  float* out = (float*)d_out;

  k_dots    <<<DOTS_GRID, 256>>>(X, Ws, Wa);
  k_edge_max<<<(EE + 255) / 256, 256>>>(targets, sources);
  k_out     <<<(TOT/4 + 255) / 256, 256>>>(targets, sources, out, 1u);
}